// round 13
// baseline (speedup 1.0000x reference)
#include <cuda_runtime.h>

// ---------------------------------------------------------------------------
// BlocCircLinear via FFT (circular-convolution theorem), all f32.
//   y[b, m*16+p] = sum_{j,q} blocks[(m-j)%512][p][q] * x[b, j*16+q]
//   = per (p,q):  y_bp = sum_q  W_pq (*) X_bq   (circular conv over 512)
// K1: forward 512-pt FFTs of x (512 seqs over j, per (b,q)) and blocks
//     (256 seqs over s, per (p,q)).  One warp per FFT, smem, textbook DIT.
// K2: per-frequency complex GEMM  Yh[f][p][b] = sum_q Wh[f][p][q] Xh[f][q][b].
// K3: inverse FFTs over f per (b,p); real part / 512 -> out.
// ~60M f32 FMA total vs 2.15G tensor MACs of the direct GEMM.
// ---------------------------------------------------------------------------

#define DIM   8192
#define BATCH 32

__device__ float2 g_xhat[512 * 512];   // [f][q*32 + b]
__device__ float2 g_what[512 * 256];   // [f][p*16 + q]
__device__ float2 g_yhat[512 * 512];   // [f][p*32 + b]

static __device__ __forceinline__ float2 cmulf(float2 a, float2 b) {
    return make_float2(a.x * b.x - a.y * b.y, a.x * b.y + a.y * b.x);
}

// In-place radix-2 DIT on buf[512] (input bit-reversed, output natural).
// tw[t] = exp(-2*pi*i*t/512), t < 256.  INV => conjugate twiddles.
template <bool INV>
static __device__ __forceinline__ void warp_fft(float2* buf, const float2* tw,
                                                int lane)
{
#pragma unroll
    for (int s = 1; s <= 9; ++s) {
        const int half = 1 << (s - 1);
#pragma unroll
        for (int it = 0; it < 8; ++it) {
            const int t  = lane + (it << 5);
            const int k  = t & (half - 1);
            const int i0 = ((t >> (s - 1)) << s) + k;
            const int i1 = i0 + half;
            float2 w = tw[k << (9 - s)];
            if (INV) w.y = -w.y;
            const float2 u = buf[i0];
            const float2 v = cmulf(w, buf[i1]);
            buf[i0] = make_float2(u.x + v.x, u.y + v.y);
            buf[i1] = make_float2(u.x - v.x, u.y - v.y);
        }
        __syncwarp();
    }
}

static __device__ __forceinline__ void build_tw(float2* tw, int tid) {
    if (tid < 256) {
        float sn, cs;
        __sincosf(-6.283185307179586f * (float)tid * (1.0f / 512.0f), &sn, &cs);
        tw[tid] = make_float2(cs, sn);
    }
}

// ---------------------------------------------------------------------------
// K1: forward FFTs.  grid 96 x 256 thr = 768 warps:
//   warp gseq < 512: x sequence (b = gseq&31, q = gseq>>5) over j.
//   warp gseq >= 512: block sequence (idx=gseq-512: p=idx>>4, q=idx&15) over s.
// ---------------------------------------------------------------------------
__global__ void __launch_bounds__(256) fft_fwd_kernel(
    const float* __restrict__ x32, const float* __restrict__ blk32)
{
    __shared__ float2 tw[256];
    __shared__ float2 buf[8][512];
    const int tid = threadIdx.x, lane = tid & 31, wid = tid >> 5;
    build_tw(tw, tid);
    __syncthreads();

    const int gseq = blockIdx.x * 8 + wid;
    float2* b_ = buf[wid];

    if (gseq < 512) {
        const int b = gseq & 31, q = gseq >> 5;
        for (int j = lane; j < 512; j += 32) {
            float v = x32[b * DIM + j * 16 + q];
            b_[__brev((unsigned)j) >> 23] = make_float2(v, 0.f);
        }
    } else {
        const int idx = gseq - 512, p = idx >> 4, q = idx & 15;
        for (int s = lane; s < 512; s += 32) {
            float v = blk32[s * 256 + p * 16 + q];
            b_[__brev((unsigned)s) >> 23] = make_float2(v, 0.f);
        }
    }
    __syncwarp();
    warp_fft<false>(b_, tw, lane);

    if (gseq < 512) {
        const int b = gseq & 31, q = gseq >> 5;
        for (int f = lane; f < 512; f += 32)
            g_xhat[f * 512 + q * 32 + b] = b_[f];
    } else {
        const int idx = gseq - 512, p = idx >> 4, q = idx & 15;
        for (int f = lane; f < 512; f += 32)
            g_what[f * 256 + p * 16 + q] = b_[f];
    }
}

// ---------------------------------------------------------------------------
// K2: per-frequency complex GEMM.  grid 128 x 128 thr = 512 warps, warp = f.
//   lane = b; each lane computes Yh[f][p][b] for p = 0..15.
// ---------------------------------------------------------------------------
__global__ void __launch_bounds__(128) spec_gemm_kernel()
{
    __shared__ float2 xsh[4][512];
    __shared__ float2 wsh[4][256];
    const int tid = threadIdx.x, lane = tid & 31, wid = tid >> 5;
    const int f = blockIdx.x * 4 + wid;
    float2* xs = xsh[wid];
    float2* ws = wsh[wid];

    for (int i = lane; i < 512; i += 32) xs[i] = g_xhat[f * 512 + i];
    for (int i = lane; i < 256; i += 32) ws[i] = g_what[f * 256 + i];
    __syncwarp();

    float2 xc[16];
#pragma unroll
    for (int q = 0; q < 16; ++q) xc[q] = xs[q * 32 + lane];

#pragma unroll
    for (int p = 0; p < 16; ++p) {
        float2 acc = make_float2(0.f, 0.f);
#pragma unroll
        for (int q = 0; q < 16; ++q) {
            const float2 w = ws[p * 16 + q];
            acc.x += w.x * xc[q].x - w.y * xc[q].y;
            acc.y += w.x * xc[q].y + w.y * xc[q].x;
        }
        g_yhat[f * 512 + p * 32 + lane] = acc;
    }
}

// ---------------------------------------------------------------------------
// K3: inverse FFTs.  grid 64 x 256 thr = 512 warps, warp = (b = idx&31,
//   p = idx>>5).  Gather Yh over f, IFFT (conj twiddles), real/512 -> out.
// ---------------------------------------------------------------------------
__global__ void __launch_bounds__(256) fft_inv_kernel(float* __restrict__ out)
{
    __shared__ float2 tw[256];
    __shared__ float2 buf[8][512];
    const int tid = threadIdx.x, lane = tid & 31, wid = tid >> 5;
    build_tw(tw, tid);
    __syncthreads();

    const int idx = blockIdx.x * 8 + wid;     // 0..511
    const int b = idx & 31, p = idx >> 5;
    float2* b_ = buf[wid];

    for (int f = lane; f < 512; f += 32)
        b_[__brev((unsigned)f) >> 23] = g_yhat[f * 512 + p * 32 + b];
    __syncwarp();
    warp_fft<true>(b_, tw, lane);

    const float inv_n = 1.0f / 512.0f;
    for (int m = lane; m < 512; m += 32)
        out[b * DIM + m * 16 + p] = b_[m].x * inv_n;
}

// ---------------------------------------------------------------------------
extern "C" void kernel_launch(void* const* d_in, const int* in_sizes, int n_in,
                              void* d_out, int out_size)
{
    const float* x   = (const float*)d_in[0];
    const float* blk = (const float*)d_in[1];
    float* out = (float*)d_out;

    fft_fwd_kernel<<<96, 256>>>(x, blk);
    spec_gemm_kernel<<<128, 128>>>();
    fft_inv_kernel<<<64, 256>>>(out);
}

// round 14
// speedup vs baseline: 1.1767x; 1.1767x over previous
#include <cuda_runtime.h>

// ---------------------------------------------------------------------------
// BlocCircLinear via FFT (circular-convolution theorem), all f32.
// R14: register+shuffle warp FFT (512 = 16 regs/lane x 32 lanes).
//   Per-lane 16-pt DIT (registers, constant W16 table), twiddle W512^(lane*k1),
//   cross-lane 32-pt DIF via shfl_xor (5 stages). No smem in the FFT at all.
//   Gmem layouts and K2 spectral GEMM identical to the R13-proven version.
// ---------------------------------------------------------------------------

#define DIM   8192
#define BATCH 32

__device__ float2 g_xhat[512 * 512];   // [f][q*32 + b]
__device__ float2 g_what[512 * 256];   // [f][p*16 + q]
__device__ float2 g_yhat[512 * 512];   // [f][p*32 + b]

static __device__ __forceinline__ float2 cmulf(float2 a, float2 b) {
    return make_float2(a.x * b.x - a.y * b.y, a.x * b.y + a.y * b.x);
}

// Register/shuffle 512-pt FFT. Input: a[t] = x[lane + 32*brev4(t)] (caller
// loads bit-reversed-r). Output: a[k1] = X[k1 + 16*brev5(lane)], k1 natural.
// INV: conjugated twiddles (no 1/N scaling).
template <bool INV>
static __device__ __forceinline__ void reg_fft(float2 a[16], int lane)
{
    // ---- per-lane 16-pt DIT over r ----
    const float SGN = INV ? 1.f : -1.f;
    const float2 W16[8] = {
        {1.f, 0.f},
        {0.9238795325f, SGN * -0.3826834324f * -1.f * -1.f}, // placeholder fix below
        {0.f, 0.f}, {0.f, 0.f}, {0.f, 0.f}, {0.f, 0.f}, {0.f, 0.f}, {0.f, 0.f}
    };
    // (table constructed explicitly to avoid sign confusion)
    float2 w16[8];
    w16[0] = make_float2(1.f, 0.f);
    w16[1] = make_float2(0.9238795325f,  SGN * 0.3826834324f);
    w16[2] = make_float2(0.7071067812f,  SGN * 0.7071067812f);
    w16[3] = make_float2(0.3826834324f,  SGN * 0.9238795325f);
    w16[4] = make_float2(0.f,            SGN * 1.f);
    w16[5] = make_float2(-0.3826834324f, SGN * 0.9238795325f);
    w16[6] = make_float2(-0.7071067812f, SGN * 0.7071067812f);
    w16[7] = make_float2(-0.9238795325f, SGN * 0.3826834324f);
    (void)W16;

#pragma unroll
    for (int s = 1; s <= 4; ++s) {
        const int half = 1 << (s - 1);
#pragma unroll
        for (int t = 0; t < 8; ++t) {
            const int k  = t & (half - 1);
            const int i0 = ((t >> (s - 1)) << s) + k;
            const int i1 = i0 + half;
            const float2 w = w16[k << (4 - s)];
            const float2 u = a[i0];
            const float2 v = cmulf(w, a[i1]);
            a[i0] = make_float2(u.x + v.x, u.y + v.y);
            a[i1] = make_float2(u.x - v.x, u.y - v.y);
        }
    }

    // ---- twiddle: a[k1] *= W512^(sign * lane * k1) ----
    {
        float sn, cs;
        __sincosf(SGN * 6.283185307179586f * (float)lane * (1.f / 512.f), &sn, &cs);
        const float2 base = make_float2(cs, sn);
        float2 w = base;
#pragma unroll
        for (int k1 = 1; k1 < 16; ++k1) {
            a[k1] = cmulf(a[k1], w);
            w = cmulf(w, base);
        }
    }

    // ---- cross-lane 32-pt DIF via shfl_xor, 5 stages ----
#pragma unroll
    for (int h = 16; h >= 1; h >>= 1) {
        const bool up = (lane & h) != 0;
        float sn, cs;
        __sincosf(SGN * 3.14159265358979f * (float)(lane & (h - 1)) / (float)h,
                  &sn, &cs);
        const float2 wst = make_float2(cs, sn);
#pragma unroll
        for (int k1 = 0; k1 < 16; ++k1) {
            float2 o;
            o.x = __shfl_xor_sync(0xFFFFFFFFu, a[k1].x, h);
            o.y = __shfl_xor_sync(0xFFFFFFFFu, a[k1].y, h);
            if (up) {
                const float2 d = make_float2(o.x - a[k1].x, o.y - a[k1].y);
                a[k1] = cmulf(wst, d);
            } else {
                a[k1] = make_float2(a[k1].x + o.x, a[k1].y + o.y);
            }
        }
    }
}

__device__ __constant__ int RB4[16] = {0,8,4,12,2,10,6,14,1,9,5,13,3,11,7,15};

// ---------------------------------------------------------------------------
// K1: forward FFTs.  grid 96 x 256 thr = 768 warps:
//   gseq < 512: x sequence (b = gseq&31, q = gseq>>5) over j.
//   gseq >= 512: block sequence (idx: p=idx>>4, q=idx&15) over s.
// ---------------------------------------------------------------------------
__global__ void __launch_bounds__(256) fft_fwd_kernel(
    const float* __restrict__ x32, const float* __restrict__ blk32)
{
    const int tid = threadIdx.x, lane = tid & 31, wid = tid >> 5;
    const int gseq = blockIdx.x * 8 + wid;
    float2 a[16];

    if (gseq < 512) {
        const int b = gseq & 31, q = gseq >> 5;
#pragma unroll
        for (int t = 0; t < 16; ++t)
            a[t] = make_float2(x32[b * DIM + (lane + 32 * RB4[t]) * 16 + q], 0.f);
        reg_fft<false>(a, lane);
        const unsigned k2 = __brev((unsigned)lane) >> 27;
#pragma unroll
        for (int k1 = 0; k1 < 16; ++k1)
            g_xhat[(k1 + 16 * k2) * 512 + q * 32 + b] = a[k1];
    } else {
        const int idx = gseq - 512, p = idx >> 4, q = idx & 15;
#pragma unroll
        for (int t = 0; t < 16; ++t)
            a[t] = make_float2(blk32[(lane + 32 * RB4[t]) * 256 + p * 16 + q], 0.f);
        reg_fft<false>(a, lane);
        const unsigned k2 = __brev((unsigned)lane) >> 27;
#pragma unroll
        for (int k1 = 0; k1 < 16; ++k1)
            g_what[(k1 + 16 * k2) * 256 + p * 16 + q] = a[k1];
    }
}

// ---------------------------------------------------------------------------
// K2: per-frequency complex GEMM (unchanged from R13-proven version).
// grid 128 x 128 thr = 512 warps, warp = f; lane = b.
// ---------------------------------------------------------------------------
__global__ void __launch_bounds__(128) spec_gemm_kernel()
{
    __shared__ float2 xsh[4][512];
    __shared__ float2 wsh[4][256];
    const int tid = threadIdx.x, lane = tid & 31, wid = tid >> 5;
    const int f = blockIdx.x * 4 + wid;
    float2* xs = xsh[wid];
    float2* ws = wsh[wid];

    for (int i = lane; i < 512; i += 32) xs[i] = g_xhat[f * 512 + i];
    for (int i = lane; i < 256; i += 32) ws[i] = g_what[f * 256 + i];
    __syncwarp();

    float2 xc[16];
#pragma unroll
    for (int q = 0; q < 16; ++q) xc[q] = xs[q * 32 + lane];

#pragma unroll
    for (int p = 0; p < 16; ++p) {
        float2 acc = make_float2(0.f, 0.f);
#pragma unroll
        for (int q = 0; q < 16; ++q) {
            const float2 w = ws[p * 16 + q];
            acc.x += w.x * xc[q].x - w.y * xc[q].y;
            acc.y += w.x * xc[q].y + w.y * xc[q].x;
        }
        g_yhat[f * 512 + p * 32 + lane] = acc;
    }
}

// ---------------------------------------------------------------------------
// K3: inverse FFTs.  grid 64 x 256 thr = 512 warps, warp = (b=idx&31, p=idx>>5).
// ---------------------------------------------------------------------------
__global__ void __launch_bounds__(256) fft_inv_kernel(float* __restrict__ out)
{
    const int tid = threadIdx.x, lane = tid & 31, wid = tid >> 5;
    const int idx = blockIdx.x * 8 + wid;     // 0..511
    const int b = idx & 31, p = idx >> 5;
    float2 a[16];

#pragma unroll
    for (int t = 0; t < 16; ++t)
        a[t] = g_yhat[(lane + 32 * RB4[t]) * 512 + p * 32 + b];

    reg_fft<true>(a, lane);

    const unsigned k2 = __brev((unsigned)lane) >> 27;
    const float inv_n = 1.0f / 512.0f;
#pragma unroll
    for (int k1 = 0; k1 < 16; ++k1) {
        const int m = k1 + 16 * (int)k2;
        out[b * DIM + m * 16 + p] = a[k1].x * inv_n;
    }
}

// ---------------------------------------------------------------------------
extern "C" void kernel_launch(void* const* d_in, const int* in_sizes, int n_in,
                              void* d_out, int out_size)
{
    const float* x   = (const float*)d_in[0];
    const float* blk = (const float*)d_in[1];
    float* out = (float*)d_out;

    fft_fwd_kernel<<<96, 256>>>(x, blk);
    spec_gemm_kernel<<<128, 128>>>();
    fft_inv_kernel<<<64, 256>>>(out);
}

// round 17
// speedup vs baseline: 1.8582x; 1.5792x over previous
#include <cuda_runtime.h>

// ---------------------------------------------------------------------------
// BlocCircLinear via FFT (circular-convolution theorem), all f32.
// R15: R14's proven register+shuffle FFT with memory/parallelism surgery:
//   - 128-thr CTAs: grids 192 / 512 / 128 (full-chip coverage).
//   - K1/K3 CTAs group warps that share cache lines (same b, adjacent q/p).
//   - all FFT-side stores transposed through padded smem -> contiguous 32B
//     chunks (100% sector efficiency). xhat layout now [f][b*16+q].
//   - K2: one CTA per frequency (512 CTAs), padded smem, coalesced I/O.
// ---------------------------------------------------------------------------

#define DIM   8192
#define BATCH 32

__device__ float2 g_xhat[512 * 512];   // [f][b*16 + q]
__device__ float2 g_what[512 * 256];   // [f][p*16 + q]
__device__ float2 g_yhat[512 * 512];   // [f][p*32 + b]

static __device__ __forceinline__ float2 cmulf(float2 a, float2 b) {
    return make_float2(a.x * b.x - a.y * b.y, a.x * b.y + a.y * b.x);
}

// Register/shuffle 512-pt FFT (R14-proven). Input: a[t] = x[lane + 32*brev4(t)].
// Output: a[k1] = X[k1 + 16*brev5(lane)]. INV: conjugated twiddles, no 1/N.
template <bool INV>
static __device__ __forceinline__ void reg_fft(float2 a[16], int lane)
{
    const float SGN = INV ? 1.f : -1.f;
    float2 w16[8];
    w16[0] = make_float2(1.f, 0.f);
    w16[1] = make_float2(0.9238795325f,  SGN * 0.3826834324f);
    w16[2] = make_float2(0.7071067812f,  SGN * 0.7071067812f);
    w16[3] = make_float2(0.3826834324f,  SGN * 0.9238795325f);
    w16[4] = make_float2(0.f,            SGN * 1.f);
    w16[5] = make_float2(-0.3826834324f, SGN * 0.9238795325f);
    w16[6] = make_float2(-0.7071067812f, SGN * 0.7071067812f);
    w16[7] = make_float2(-0.9238795325f, SGN * 0.3826834324f);

#pragma unroll
    for (int s = 1; s <= 4; ++s) {
        const int half = 1 << (s - 1);
#pragma unroll
        for (int t = 0; t < 8; ++t) {
            const int k  = t & (half - 1);
            const int i0 = ((t >> (s - 1)) << s) + k;
            const int i1 = i0 + half;
            const float2 w = w16[k << (4 - s)];
            const float2 u = a[i0];
            const float2 v = cmulf(w, a[i1]);
            a[i0] = make_float2(u.x + v.x, u.y + v.y);
            a[i1] = make_float2(u.x - v.x, u.y - v.y);
        }
    }
    {
        float sn, cs;
        __sincosf(SGN * 6.283185307179586f * (float)lane * (1.f / 512.f), &sn, &cs);
        const float2 base = make_float2(cs, sn);
        float2 w = base;
#pragma unroll
        for (int k1 = 1; k1 < 16; ++k1) {
            a[k1] = cmulf(a[k1], w);
            w = cmulf(w, base);
        }
    }
#pragma unroll
    for (int h = 16; h >= 1; h >>= 1) {
        const bool up = (lane & h) != 0;
        float sn, cs;
        __sincosf(SGN * 3.14159265358979f * (float)(lane & (h - 1)) / (float)h,
                  &sn, &cs);
        const float2 wst = make_float2(cs, sn);
#pragma unroll
        for (int k1 = 0; k1 < 16; ++k1) {
            float2 o;
            o.x = __shfl_xor_sync(0xFFFFFFFFu, a[k1].x, h);
            o.y = __shfl_xor_sync(0xFFFFFFFFu, a[k1].y, h);
            if (up) {
                const float2 d = make_float2(o.x - a[k1].x, o.y - a[k1].y);
                a[k1] = cmulf(wst, d);
            } else {
                a[k1] = make_float2(a[k1].x + o.x, a[k1].y + o.y);
            }
        }
    }
}

__device__ __constant__ int RB4[16] = {0,8,4,12,2,10,6,14,1,9,5,13,3,11,7,15};

// ---------------------------------------------------------------------------
// K1: forward FFTs. grid 192 x 128 thr (4 warps).
//   c < 128 : x.  b = c>>2, q = (c&3)*4 + wid.   (warps share cache lines)
//   c >= 128: blocks. idx=c-128: p = idx>>2, q = (idx&3)*4 + wid.
// Stores transposed through padded smem -> 32B contiguous chunks.
// ---------------------------------------------------------------------------
__global__ void __launch_bounds__(128) fft_fwd_kernel(
    const float* __restrict__ x32, const float* __restrict__ blk32)
{
    __shared__ float2 sbuf[4][544];           // pad: idx = f + (f>>4)
    const int tid = threadIdx.x, lane = tid & 31, wid = tid >> 5;
    const int c = blockIdx.x;
    float2 a[16];

    if (c < 128) {
        const int b = c >> 2, qg = (c & 3) * 4, q = qg + wid;
#pragma unroll
        for (int t = 0; t < 16; ++t)
            a[t] = make_float2(x32[b * DIM + (lane + 32 * RB4[t]) * 16 + q], 0.f);
        reg_fft<false>(a, lane);
        const int k2 = (int)(__brev((unsigned)lane) >> 27);
#pragma unroll
        for (int k1 = 0; k1 < 16; ++k1)
            sbuf[wid][k1 + 17 * k2] = a[k1];
        __syncthreads();
        // store: thread t covers f = t, t+128, t+256, t+384; 4 q's contiguous
#pragma unroll
        for (int rep = 0; rep < 4; ++rep) {
            const int f = tid + rep * 128;
            const int fp = f + (f >> 4);
            float2 v0 = sbuf[0][fp], v1 = sbuf[1][fp];
            float2 v2 = sbuf[2][fp], v3 = sbuf[3][fp];
            float4* dst = reinterpret_cast<float4*>(
                g_xhat + f * 512 + b * 16 + qg);
            dst[0] = make_float4(v0.x, v0.y, v1.x, v1.y);
            dst[1] = make_float4(v2.x, v2.y, v3.x, v3.y);
        }
    } else {
        const int idx = c - 128, p = idx >> 2, qg = (idx & 3) * 4, q = qg + wid;
#pragma unroll
        for (int t = 0; t < 16; ++t)
            a[t] = make_float2(blk32[(lane + 32 * RB4[t]) * 256 + p * 16 + q], 0.f);
        reg_fft<false>(a, lane);
        const int k2 = (int)(__brev((unsigned)lane) >> 27);
#pragma unroll
        for (int k1 = 0; k1 < 16; ++k1)
            sbuf[wid][k1 + 17 * k2] = a[k1];
        __syncthreads();
#pragma unroll
        for (int rep = 0; rep < 4; ++rep) {
            const int f = tid + rep * 128;
            const int fp = f + (f >> 4);
            float2 v0 = sbuf[0][fp], v1 = sbuf[1][fp];
            float2 v2 = sbuf[2][fp], v3 = sbuf[3][fp];
            float4* dst = reinterpret_cast<float4*>(
                g_what + f * 256 + p * 16 + qg);
            dst[0] = make_float4(v0.x, v0.y, v1.x, v1.y);
            dst[1] = make_float4(v2.x, v2.y, v3.x, v3.y);
        }
    }
}

// ---------------------------------------------------------------------------
// K2: per-frequency complex GEMM. grid 512 x 128 thr; CTA = frequency f,
// warp = 4 consecutive p. lane = b. Coalesced loads; padded smem (17-stride).
// ---------------------------------------------------------------------------
__global__ void __launch_bounds__(128) spec_gemm_kernel()
{
    __shared__ float2 xsh[544];               // [b*17 + q]
    __shared__ float2 wsh[256];               // [p*16 + q]
    const int tid = threadIdx.x, lane = tid & 31, wid = tid >> 5;
    const int f = blockIdx.x;

    for (int i = tid; i < 512; i += 128)
        xsh[i + (i >> 4)] = g_xhat[f * 512 + i];
    for (int i = tid; i < 256; i += 128)
        wsh[i] = g_what[f * 256 + i];
    __syncthreads();

    float2 xc[16];
#pragma unroll
    for (int q = 0; q < 16; ++q) xc[q] = xsh[lane * 17 + q];

    const int p0 = wid * 4;
#pragma unroll
    for (int pp = 0; pp < 4; ++pp) {
        const int p = p0 + pp;
        float2 acc = make_float2(0.f, 0.f);
#pragma unroll
        for (int q = 0; q < 16; ++q) {
            const float2 w = wsh[p * 16 + q];
            acc.x += w.x * xc[q].x - w.y * xc[q].y;
            acc.y += w.x * xc[q].y + w.y * xc[q].x;
        }
        g_yhat[f * 512 + p * 32 + lane] = acc;
    }
}

// ---------------------------------------------------------------------------
// K3: inverse FFTs. grid 128 x 128 thr (4 warps). CTA: b = c>>2,
// p = (c&3)*4 + wid. Output transposed through smem -> 16B float4 stores.
// ---------------------------------------------------------------------------
__global__ void __launch_bounds__(128) fft_inv_kernel(float* __restrict__ out)
{
    __shared__ float sbuf[4][544];            // pad: idx = m + (m>>4)
    const int tid = threadIdx.x, lane = tid & 31, wid = tid >> 5;
    const int c = blockIdx.x;
    const int b = c >> 2, pg = (c & 3) * 4, p = pg + wid;
    float2 a[16];

#pragma unroll
    for (int t = 0; t < 16; ++t)
        a[t] = g_yhat[(lane + 32 * RB4[t]) * 512 + p * 32 + b];

    reg_fft<true>(a, lane);

    const int k2 = (int)(__brev((unsigned)lane) >> 27);
    const float inv_n = 1.0f / 512.0f;
#pragma unroll
    for (int k1 = 0; k1 < 16; ++k1)
        sbuf[wid][k1 + 17 * k2] = a[k1].x * inv_n;
    __syncthreads();

    // store: thread t covers m = t, t+128, t+256, t+384; 4 p's contiguous
#pragma unroll
    for (int rep = 0; rep < 4; ++rep) {
        const int m = tid + rep * 128;
        const int mp = m + (m >> 4);
        *reinterpret_cast<float4*>(out + b * DIM + m * 16 + pg) =
            make_float4(sbuf[0][mp], sbuf[1][mp], sbuf[2][mp], sbuf[3][mp]);
    }
}

// ---------------------------------------------------------------------------
extern "C" void kernel_launch(void* const* d_in, const int* in_sizes, int n_in,
                              void* d_out, int out_size)
{
    const float* x   = (const float*)d_in[0];
    const float* blk = (const float*)d_in[1];
    float* out = (float*)d_out;

    fft_fwd_kernel<<<192, 128>>>(x, blk);
    spec_gemm_kernel<<<512, 128>>>();
    fft_inv_kernel<<<128, 128>>>(out);
}